// round 13
// baseline (speedup 1.0000x reference)
#include <cuda_runtime.h>

#define NCL 127            // active clusters (reference excludes the last)
#define NPTS 1024
#define SLABS 32           // row slabs per cluster (32 rows each)
#define THREADS 128        // 4 warps; warp owns 8 rows
#define R 8                // rows per warp (broadcast across lanes)
#define BIGF 3.4e38f

__device__ float g_col[NCL * SLABS * NPTS];   // [c][slab][j] colmin partials
__device__ float g_rowsum[NCL * SLABS];
__device__ float g_cl[NCL];

// CTA = (cluster c, 32-row slab). Warp w owns rows slab*32 + w*8..+7 (row data
// broadcast in registers); lane owns column j = 32*s + lane at step s.
//   d(r,j) = fma(-2ax,bx, fma(-2ay,by, fma(-2az,bz, |a_r|^2 + |b_j|^2)))
// Row-min: m[r] = fmin(m[r], d)           (lane-private, shfl-merged at end)
// Col-min: 7-FMNMX tree over the 8 rows   (lane-private, one STS per step)
// Columns staged in smem as float4 (x,y,z,|b|^2); next column prefetched into
// registers so the LDS latency is hidden behind the FMA block.
__global__ void __launch_bounds__(THREADS)
chamfer_main(const float* __restrict__ in_pts,
             const float* __restrict__ out_pts) {
    const int c    = blockIdx.x >> 5;
    const int slab = blockIdx.x & (SLABS - 1);

    const float* ap = in_pts  + (size_t)c * NPTS * 3;
    const float* bp = out_pts + (size_t)c * NPTS * 3;

    __shared__ float4 sb[NPTS];        // (x,y,z,|b|^2) per column, 16KB
    __shared__ float  wcol[4][NPTS];   // per-warp colmin per col, 16KB
    __shared__ float  redbuf[4];

    const int tid  = threadIdx.x;
    const int wid  = tid >> 5;
    const int lane = tid & 31;

    // Stage columns + norms.
    for (int j = tid; j < NPTS; j += THREADS) {
        float x = bp[3 * j + 0];
        float y = bp[3 * j + 1];
        float z = bp[3 * j + 2];
        sb[j] = make_float4(x, y, z, fmaf(x, x, fmaf(y, y, z * z)));
    }

    // Load this warp's 8 rows (96B, 16B-aligned) via 6 uniform LDG.128.
    const float4* arow4 =
        (const float4*)(ap + ((size_t)slab * 32 + wid * R) * 3);
    float rf[24];
    {
        float4 rv[6];
#pragma unroll
        for (int k = 0; k < 6; k++) rv[k] = arow4[k];
#pragma unroll
        for (int k = 0; k < 6; k++) {
            rf[4 * k + 0] = rv[k].x;
            rf[4 * k + 1] = rv[k].y;
            rf[4 * k + 2] = rv[k].z;
            rf[4 * k + 3] = rv[k].w;
        }
    }
    float a2x[R], a2y[R], a2z[R], an[R], m[R];
#pragma unroll
    for (int r = 0; r < R; r++) {
        float x = rf[3 * r + 0];
        float y = rf[3 * r + 1];
        float z = rf[3 * r + 2];
        a2x[r] = -2.0f * x;
        a2y[r] = -2.0f * y;
        a2z[r] = -2.0f * z;
        an[r]  = fmaf(x, x, fmaf(y, y, z * z));
        m[r]   = BIGF;
    }
    __syncthreads();

    float* mycol = wcol[wid];

    // Main loop: 32 steps; lane's col j = 32*s + lane. Next b prefetched.
    float4 b = sb[lane];
#pragma unroll 4
    for (int s = 0; s < NPTS / 32; s++) {
        float4 bn = sb[(((s + 1) & 31) << 5) | lane];   // wraps at end; unused

        float d0 = fmaf(a2x[0], b.x, fmaf(a2y[0], b.y, fmaf(a2z[0], b.z, an[0] + b.w)));
        float d1 = fmaf(a2x[1], b.x, fmaf(a2y[1], b.y, fmaf(a2z[1], b.z, an[1] + b.w)));
        m[0] = fminf(m[0], d0);
        m[1] = fminf(m[1], d1);
        float e0 = fminf(d0, d1);
        float d2 = fmaf(a2x[2], b.x, fmaf(a2y[2], b.y, fmaf(a2z[2], b.z, an[2] + b.w)));
        float d3 = fmaf(a2x[3], b.x, fmaf(a2y[3], b.y, fmaf(a2z[3], b.z, an[3] + b.w)));
        m[2] = fminf(m[2], d2);
        m[3] = fminf(m[3], d3);
        float e1 = fminf(d2, d3);
        float d4 = fmaf(a2x[4], b.x, fmaf(a2y[4], b.y, fmaf(a2z[4], b.z, an[4] + b.w)));
        float d5 = fmaf(a2x[5], b.x, fmaf(a2y[5], b.y, fmaf(a2z[5], b.z, an[5] + b.w)));
        m[4] = fminf(m[4], d4);
        m[5] = fminf(m[5], d5);
        float e2 = fminf(d4, d5);
        float d6 = fmaf(a2x[6], b.x, fmaf(a2y[6], b.y, fmaf(a2z[6], b.z, an[6] + b.w)));
        float d7 = fmaf(a2x[7], b.x, fmaf(a2y[7], b.y, fmaf(a2z[7], b.z, an[7] + b.w)));
        m[6] = fminf(m[6], d6);
        m[7] = fminf(m[7], d7);
        float e3 = fminf(d6, d7);

        mycol[(s << 5) | lane] = fminf(fminf(e0, e1), fminf(e2, e3));
        b = bn;
    }

    // Row-min merge across lanes: butterfly per row, then sum over rows.
    float rs = 0.0f;
#pragma unroll
    for (int r = 0; r < R; r++) {
        float v = m[r];
#pragma unroll
        for (int off = 16; off > 0; off >>= 1)
            v = fminf(v, __shfl_xor_sync(0xffffffffu, v, off));
        rs += v;
    }
    if (lane == 0) redbuf[wid] = rs;
    __syncthreads();

    // Col phase: merge 4 warps' colmins, store slab partial.
    float* gout = g_col + ((size_t)c * SLABS + slab) * NPTS;
    for (int col = tid; col < NPTS; col += THREADS) {
        float v = fminf(fminf(wcol[0][col], wcol[1][col]),
                        fminf(wcol[2][col], wcol[3][col]));
        gout[col] = v;
    }
    if (tid == 0)
        g_rowsum[blockIdx.x] =
            (redbuf[0] + redbuf[1]) + (redbuf[2] + redbuf[3]);
}

// Per-cluster: min colmin partials over 32 slabs, sum over cols, add row terms.
__global__ void cluster_reduce_kernel() {
    const int c   = blockIdx.x;      // 0..126
    const int tid = threadIdx.x;     // 512
    const float* base = g_col + (size_t)c * SLABS * NPTS;

    float s = 0.0f;
    for (int col = tid; col < NPTS; col += 512) {
        float v = BIGF;
#pragma unroll
        for (int sl = 0; sl < SLABS; sl++)
            v = fminf(v, base[sl * NPTS + col]);
        s += v;
    }
    if (tid < SLABS) s += g_rowsum[c * SLABS + tid];

#pragma unroll
    for (int off = 16; off > 0; off >>= 1)
        s += __shfl_down_sync(0xffffffffu, s, off);
    __shared__ float ws[16];
    if ((tid & 31) == 0) ws[tid >> 5] = s;
    __syncthreads();
    if (tid < 16) {
        s = ws[tid];
#pragma unroll
        for (int off = 8; off > 0; off >>= 1)
            s += __shfl_down_sync(0xffffu, s, off);
        if (tid == 0) g_cl[c] = s;
    }
}

__global__ void final_sum_kernel(float* __restrict__ out) {
    const int tid = threadIdx.x;     // 128
    float s = (tid < NCL) ? g_cl[tid] : 0.0f;
#pragma unroll
    for (int off = 16; off > 0; off >>= 1)
        s += __shfl_down_sync(0xffffffffu, s, off);
    __shared__ float ws[4];
    if ((tid & 31) == 0) ws[tid >> 5] = s;
    __syncthreads();
    if (tid == 0) out[0] = (ws[0] + ws[1]) + (ws[2] + ws[3]);
}

extern "C" void kernel_launch(void* const* d_in, const int* in_sizes, int n_in,
                              void* d_out, int out_size) {
    const float* in_pts  = (const float*)d_in[0];
    const float* out_pts = (const float*)d_in[2];
    float* out = (float*)d_out;

    chamfer_main<<<NCL * SLABS, THREADS>>>(in_pts, out_pts);
    cluster_reduce_kernel<<<NCL, 512>>>();
    final_sum_kernel<<<1, 128>>>(out);
}